// round 1
// baseline (speedup 1.0000x reference)
#include <cuda_runtime.h>
#include <math.h>
#include <float.h>

#define NW   1024
#define NOCT 12
#define NCOL 16
#define NB   8

// ---- static device scratch (no runtime allocation) ----
__device__ float         g_hxn[NOCT * NW];
__device__ unsigned      g_nmin, g_nmax, g_omin, g_omax;
__device__ unsigned char g_idx[NW * NW];

// 1.5^o, all exactly representable in fp32 (matches jnp float32 constants)
__constant__ float c_pw[NOCT] = {
    1.0f, 1.5f, 2.25f, 3.375f, 5.0625f, 7.59375f, 11.390625f,
    17.0859375f, 25.62890625f, 38.443359375f, 57.6650390625f, 86.49755859375f
};

__global__ void k_init() {
    g_nmin = 0x7f7fffffu; g_nmax = 0u;
    g_omin = 0x7f7fffffu; g_omax = 0u;
}

// One block per octave, 1024 threads = 1024 x-samples.
// Reproduces: hx = sin(x * (f*pi)); hxn = (hx - min)/(max - min) in fp32.
__global__ void k_octaves() {
    int i = threadIdx.x;
    int o = blockIdx.x;
    __shared__ float smn[32], smx[32];

    // x_i = fl(i * fl(1/1023))  (jnp.linspace via iota * delta)
    float xi = __fmul_rn((float)i, 1.0f / 1023.0f);
    // scale = fl((FREQ * 2^o) * pi) computed in double then cast (weak-typed scalar)
    float scale = (float)((double)(320 << o) * 3.14159265358979323846);
    float arg = __fmul_rn(xi, scale);            // exact fp32 product, matches XLA
    float s = (float)sin((double)arg);           // accurate sin (fast-math safe)

    float mn = s, mx = s;
    #pragma unroll
    for (int off = 16; off; off >>= 1) {
        mn = fminf(mn, __shfl_xor_sync(0xffffffffu, mn, off));
        mx = fmaxf(mx, __shfl_xor_sync(0xffffffffu, mx, off));
    }
    if ((i & 31) == 0) { smn[i >> 5] = mn; smx[i >> 5] = mx; }
    __syncthreads();
    if (i < 32) {
        mn = smn[i]; mx = smx[i];
        #pragma unroll
        for (int off = 16; off; off >>= 1) {
            mn = fminf(mn, __shfl_xor_sync(0xffffffffu, mn, off));
            mx = fmaxf(mx, __shfl_xor_sync(0xffffffffu, mx, off));
        }
        if (i == 0) { smn[0] = mn; smx[0] = mx; }
    }
    __syncthreads();
    float m0 = smn[0], m1 = smx[0];
    g_hxn[o * NW + i] = __fdiv_rn(__fsub_rn(s, m0), __fsub_rn(m1, m0));
}

// noise[i,j] replicated with the reference's exact fp32 accumulation order:
// noise = noise + (hxn_i + hxn_j) * 1.5^o
__device__ __forceinline__ float noise_at(int i, int j) {
    float n = 0.0f;
    #pragma unroll
    for (int o = 0; o < NOCT; o++) {
        float a = __ldg(&g_hxn[o * NW + i]);
        float b = __ldg(&g_hxn[o * NW + j]);
        n = __fadd_rn(n, __fmul_rn(__fadd_rn(a, b), c_pw[o]));
    }
    return n;
}

__global__ void k_nminmax() {
    int p = blockIdx.x * blockDim.x + threadIdx.x;
    float n = noise_at(p >> 10, p & 1023);
    float mn = n, mx = n;
    #pragma unroll
    for (int off = 16; off; off >>= 1) {
        mn = fminf(mn, __shfl_xor_sync(0xffffffffu, mn, off));
        mx = fmaxf(mx, __shfl_xor_sync(0xffffffffu, mx, off));
    }
    __shared__ float smn[8], smx[8];
    int lane = threadIdx.x & 31, w = threadIdx.x >> 5;
    if (lane == 0) { smn[w] = mn; smx[w] = mx; }
    __syncthreads();
    if (threadIdx.x == 0) {
        mn = smn[0]; mx = smx[0];
        #pragma unroll
        for (int q = 1; q < 8; q++) { mn = fminf(mn, smn[q]); mx = fmaxf(mx, smx[q]); }
        atomicMin(&g_nmin, __float_as_uint(mn));   // values are >= 0
        atomicMax(&g_nmax, __float_as_uint(mx));
    }
}

__global__ void k_makeidx() {
    int p = blockIdx.x * blockDim.x + threadIdx.x;
    float n = noise_at(p >> 10, p & 1023);
    float mn = __uint_as_float(g_nmin);
    float mx = __uint_as_float(g_nmax);
    float v = __fdiv_rn(__fsub_rn(n, mn), __fsub_rn(mx, mn));
    // jnp.round = round-half-even = rintf
    g_idx[p] = (unsigned char)(int)rintf(__fmul_rn(v, 15.0f));
}

// 5x5 box blur of palette-mapped image, all 8 batches x 3 channels at once.
// Pass WRITE=false: global min/max reduction. Pass WRITE=true: normalize+store.
template <bool WRITE>
__global__ void k_blur(const float* __restrict__ colors, float* __restrict__ out) {
    __shared__ float colS[NCOL][NB * 3];       // [k][b*3+c]
    __shared__ unsigned char tile[12][36];     // 8x32 tile + halo 2

    int tx = threadIdx.x, ty = threadIdx.y;    // blockDim = (32, 8)
    int t = ty * 32 + tx;

    for (int q = t; q < NB * NCOL * 3; q += 256) {
        int b = q / 48, rem = q % 48, k = rem / 3, c = rem % 3;
        colS[k][b * 3 + c] = colors[q];
    }
    int bi0 = blockIdx.y * 8, bj0 = blockIdx.x * 32;
    for (int q = t; q < 12 * 36; q += 256) {
        int r = q / 36, cc = q % 36;
        int gi = bi0 + r - 2, gj = bj0 + cc - 2;
        unsigned char v = 255;                 // zero-pad sentinel
        if ((unsigned)gi < (unsigned)NW && (unsigned)gj < (unsigned)NW)
            v = g_idx[gi * NW + gj];
        tile[r][cc] = v;
    }
    __syncthreads();

    // 16-bin neighborhood histogram packed in two u64 (8-bit fields, counts<=25)
    unsigned long long lo = 0ull, hi = 0ull;
    #pragma unroll
    for (int dy = 0; dy < 5; dy++)
        #pragma unroll
        for (int dx = 0; dx < 5; dx++) {
            int k = tile[ty + dy][tx + dx];
            if (k < 16) {
                unsigned long long one = 1ull << ((k & 7) * 8);
                if (k < 8) lo += one; else hi += one;
            }
        }

    float cnt[NCOL];
    #pragma unroll
    for (int k = 0; k < NCOL; k++)
        cnt[k] = (float)((unsigned)((k < 8 ? lo : hi) >> ((k & 7) * 8)) & 0xffu);

    float acc[NB * 3];
    #pragma unroll
    for (int q = 0; q < NB * 3; q++) acc[q] = 0.0f;
    #pragma unroll
    for (int k = 0; k < NCOL; k++) {
        float f = cnt[k];
        #pragma unroll
        for (int q = 0; q < NB * 3; q++) acc[q] += f * colS[k][q];
    }

    const float KW = 0.04f;  // fl(1/25)

    if (!WRITE) {
        float lmn = FLT_MAX, lmx = 0.0f;
        #pragma unroll
        for (int q = 0; q < NB * 3; q++) {
            float v = acc[q] * KW;
            lmn = fminf(lmn, v); lmx = fmaxf(lmx, v);
        }
        #pragma unroll
        for (int off = 16; off; off >>= 1) {
            lmn = fminf(lmn, __shfl_xor_sync(0xffffffffu, lmn, off));
            lmx = fmaxf(lmx, __shfl_xor_sync(0xffffffffu, lmx, off));
        }
        __shared__ float smn[8], smx[8];
        int lane = t & 31, w = t >> 5;
        if (lane == 0) { smn[w] = lmn; smx[w] = lmx; }
        __syncthreads();
        if (t == 0) {
            lmn = smn[0]; lmx = smx[0];
            #pragma unroll
            for (int q = 1; q < 8; q++) { lmn = fminf(lmn, smn[q]); lmx = fmaxf(lmx, smx[q]); }
            atomicMin(&g_omin, __float_as_uint(lmn));   // values >= 0
            atomicMax(&g_omax, __float_as_uint(lmx));
        }
    } else {
        float mn = __uint_as_float(g_omin);
        float mx = __uint_as_float(g_omax);
        float inv = 1.0f / (mx - mn);
        int i = bi0 + ty, j = bj0 + tx;
        #pragma unroll
        for (int b = 0; b < NB; b++) {
            int base = ((b * NW + i) * NW + j) * 3;
            out[base + 0] = (acc[b * 3 + 0] * KW - mn) * inv;
            out[base + 1] = (acc[b * 3 + 1] * KW - mn) * inv;
            out[base + 2] = (acc[b * 3 + 2] * KW - mn) * inv;
        }
    }
}

extern "C" void kernel_launch(void* const* d_in, const int* in_sizes, int n_in,
                              void* d_out, int out_size) {
    (void)in_sizes; (void)n_in; (void)out_size;
    const float* colors = (const float*)d_in[0];
    float* out = (float*)d_out;

    k_init<<<1, 1>>>();
    k_octaves<<<NOCT, NW>>>();
    k_nminmax<<<(NW * NW) / 256, 256>>>();
    k_makeidx<<<(NW * NW) / 256, 256>>>();

    dim3 blk(32, 8);
    dim3 grd(NW / 32, NW / 8);
    k_blur<false><<<grd, blk>>>(colors, out);
    k_blur<true><<<grd, blk>>>(colors, out);
}

// round 2
// speedup vs baseline: 1.0431x; 1.0431x over previous
#include <cuda_runtime.h>
#include <math.h>
#include <float.h>

#define NW   1024
#define NOCT 12
#define NCOL 16
#define NB   8

// ---- static device scratch ----
__device__ float         g_hxn[NOCT * NW];
__device__ unsigned      g_nmin, g_nmax, g_omin, g_omax;
__device__ unsigned char g_idx[NW * NW];

__constant__ float c_pw[NOCT] = {
    1.0f, 1.5f, 2.25f, 3.375f, 5.0625f, 7.59375f, 11.390625f,
    17.0859375f, 25.62890625f, 38.443359375f, 57.6650390625f, 86.49755859375f
};

// ---- packed f32x2 helpers (Blackwell) ----
__device__ __forceinline__ void fma2(unsigned long long& d, unsigned long long a, unsigned long long b) {
    asm("fma.rn.f32x2 %0, %1, %2, %0;" : "+l"(d) : "l"(a), "l"(b));
}
__device__ __forceinline__ unsigned long long pack2(float f) {
    unsigned long long r; asm("mov.b64 %0, {%1, %1};" : "=l"(r) : "f"(f)); return r;
}
__device__ __forceinline__ unsigned long long pk(float a, float b) {
    unsigned long long r; asm("mov.b64 %0, {%1, %2};" : "=l"(r) : "f"(a), "f"(b)); return r;
}
__device__ __forceinline__ void unpack2(unsigned long long v, float& a, float& b) {
    asm("mov.b64 {%0, %1}, %2;" : "=f"(a), "=f"(b) : "l"(v));
}

// One block per octave; also does the global init (used only by later kernels).
__global__ void k_octaves() {
    int i = threadIdx.x;
    int o = blockIdx.x;
    if (o == 0 && i == 0) {
        g_nmin = 0x7f7fffffu; g_nmax = 0u;
        g_omin = 0x7f7fffffu; g_omax = 0u;
    }
    __shared__ float smn[32], smx[32];

    float xi = __fmul_rn((float)i, 1.0f / 1023.0f);
    float scale = (float)((double)(320 << o) * 3.14159265358979323846);
    float arg = __fmul_rn(xi, scale);
    float s = (float)sin((double)arg);

    float mn = s, mx = s;
    #pragma unroll
    for (int off = 16; off; off >>= 1) {
        mn = fminf(mn, __shfl_xor_sync(0xffffffffu, mn, off));
        mx = fmaxf(mx, __shfl_xor_sync(0xffffffffu, mx, off));
    }
    if ((i & 31) == 0) { smn[i >> 5] = mn; smx[i >> 5] = mx; }
    __syncthreads();
    if (i < 32) {
        mn = smn[i]; mx = smx[i];
        #pragma unroll
        for (int off = 16; off; off >>= 1) {
            mn = fminf(mn, __shfl_xor_sync(0xffffffffu, mn, off));
            mx = fmaxf(mx, __shfl_xor_sync(0xffffffffu, mx, off));
        }
        if (i == 0) { smn[0] = mn; smx[0] = mx; }
    }
    __syncthreads();
    g_hxn[o * NW + i] = __fdiv_rn(__fsub_rn(s, smn[0]), __fsub_rn(smx[0], smn[0]));
}

// Exact-fp32 noise replication (reference accumulation order).
__device__ __forceinline__ float noise_px(int i, int j) {
    float n = 0.0f;
    #pragma unroll
    for (int o = 0; o < NOCT; o++) {
        float a = __ldg(&g_hxn[o * NW + i]);
        float b = __ldg(&g_hxn[o * NW + j]);
        n = __fadd_rn(n, __fmul_rn(__fadd_rn(a, b), c_pw[o]));
    }
    return n;
}

// 4 pixels/thread (float4 loads along j) -> global noise min/max
__global__ void k_nminmax() {
    int g = blockIdx.x * 256 + threadIdx.x;
    int i = g >> 8, j0 = (g & 255) << 2;
    float n0 = 0.f, n1 = 0.f, n2 = 0.f, n3 = 0.f;
    #pragma unroll
    for (int o = 0; o < NOCT; o++) {
        float a = __ldg(&g_hxn[o * NW + i]);
        float4 b = __ldg((const float4*)&g_hxn[o * NW + j0]);
        float p = c_pw[o];
        n0 = __fadd_rn(n0, __fmul_rn(__fadd_rn(a, b.x), p));
        n1 = __fadd_rn(n1, __fmul_rn(__fadd_rn(a, b.y), p));
        n2 = __fadd_rn(n2, __fmul_rn(__fadd_rn(a, b.z), p));
        n3 = __fadd_rn(n3, __fmul_rn(__fadd_rn(a, b.w), p));
    }
    float mn = fminf(fminf(n0, n1), fminf(n2, n3));
    float mx = fmaxf(fmaxf(n0, n1), fmaxf(n2, n3));
    #pragma unroll
    for (int off = 16; off; off >>= 1) {
        mn = fminf(mn, __shfl_xor_sync(0xffffffffu, mn, off));
        mx = fmaxf(mx, __shfl_xor_sync(0xffffffffu, mx, off));
    }
    __shared__ float smn[8], smx[8];
    int lane = threadIdx.x & 31, w = threadIdx.x >> 5;
    if (lane == 0) { smn[w] = mn; smx[w] = mx; }
    __syncthreads();
    if (threadIdx.x == 0) {
        mn = smn[0]; mx = smx[0];
        #pragma unroll
        for (int q = 1; q < 8; q++) { mn = fminf(mn, smn[q]); mx = fmaxf(mx, smx[q]); }
        atomicMin(&g_nmin, __float_as_uint(mn));
        atomicMax(&g_nmax, __float_as_uint(mx));
    }
}

// histogram (two u64, 8-bit fields) + packed-FFMA2 palette dot
__device__ __forceinline__ void hist_dot(
    const unsigned char (*tile)[36], const float2 (*colS)[12],
    int tx, int ty, unsigned long long acc[12])
{
    unsigned long long lo = 0ull, hi = 0ull;
    #pragma unroll
    for (int dy = 0; dy < 5; dy++)
        #pragma unroll
        for (int dx = 0; dx < 5; dx++) {
            int k = tile[ty + dy][tx + dx];
            if (k < 16) {
                unsigned long long one = 1ull << ((k & 7) * 8);
                if (k < 8) lo += one; else hi += one;
            }
        }
    #pragma unroll
    for (int q = 0; q < 12; q++) acc[q] = 0ull;
    #pragma unroll
    for (int k = 0; k < NCOL; k++) {
        unsigned c = (unsigned)(((k < 8 ? lo : hi) >> ((k & 7) * 8)) & 0xffu);
        unsigned long long f2 = pack2((float)c);
        const float4* cp = (const float4*)&colS[k][0];
        #pragma unroll
        for (int m = 0; m < 6; m++) {
            float4 v = cp[m];
            fma2(acc[2 * m + 0], f2, pk(v.x, v.y));
            fma2(acc[2 * m + 1], f2, pk(v.z, v.w));
        }
    }
}

__device__ __forceinline__ void load_palette(const float* __restrict__ colors,
                                             float2 (*colS)[12], int t) {
    // colS[k] linear float layout: q = b*3 + c ; colors layout [b][k][c]
    for (int idx = t; idx < NCOL * NB * 3; idx += 256) {
        int k = idx / 24, q = idx % 24;
        int b = q / 3, c = q % 3;
        ((float*)colS)[k * 24 + q] = colors[b * 48 + k * 3 + c];
    }
}

// Pass A: inline idx computation (also persists g_idx), min/max of blurred output.
__global__ void __launch_bounds__(256) k_blurA(const float* __restrict__ colors) {
    __shared__ float2 colS[NCOL][12];
    __shared__ unsigned char tile[12][36];

    int tx = threadIdx.x, ty = threadIdx.y;
    int t = ty * 32 + tx;
    load_palette(colors, colS, t);

    float nmn = __uint_as_float(g_nmin);
    float nmx = __uint_as_float(g_nmax);
    int bi0 = blockIdx.y * 8, bj0 = blockIdx.x * 32;
    for (int q = t; q < 12 * 36; q += 256) {
        int r = q / 36, cc = q % 36;
        int gi = bi0 + r - 2, gj = bj0 + cc - 2;
        unsigned char v = 255;
        if ((unsigned)gi < (unsigned)NW && (unsigned)gj < (unsigned)NW) {
            float n = noise_px(gi, gj);
            float val = __fdiv_rn(__fsub_rn(n, nmn), __fsub_rn(nmx, nmn));
            v = (unsigned char)(int)rintf(__fmul_rn(val, 15.0f));
            if (r >= 2 && r < 10 && cc >= 2 && cc < 34)
                g_idx[gi * NW + gj] = v;
        }
        tile[r][cc] = v;
    }
    __syncthreads();

    unsigned long long acc[12];
    hist_dot(tile, colS, tx, ty, acc);

    float lmn = FLT_MAX, lmx = 0.0f;
    #pragma unroll
    for (int q = 0; q < 12; q++) {
        float a, b; unpack2(acc[q], a, b);
        lmn = fminf(lmn, fminf(a, b));
        lmx = fmaxf(lmx, fmaxf(a, b));
    }
    const float KW = 0.04f;
    lmn *= KW; lmx *= KW;
    #pragma unroll
    for (int off = 16; off; off >>= 1) {
        lmn = fminf(lmn, __shfl_xor_sync(0xffffffffu, lmn, off));
        lmx = fmaxf(lmx, __shfl_xor_sync(0xffffffffu, lmx, off));
    }
    __shared__ float smn[8], smx[8];
    int lane = t & 31, w = t >> 5;
    if (lane == 0) { smn[w] = lmn; smx[w] = lmx; }
    __syncthreads();
    if (t == 0) {
        lmn = smn[0]; lmx = smx[0];
        #pragma unroll
        for (int q = 1; q < 8; q++) { lmn = fminf(lmn, smn[q]); lmx = fmaxf(lmx, smx[q]); }
        atomicMin(&g_omin, __float_as_uint(lmn));
        atomicMax(&g_omax, __float_as_uint(lmx));
    }
}

// Pass B: recompute blur from g_idx, normalize, coalesced float4 store via smem stage.
__global__ void __launch_bounds__(256) k_blurB(const float* __restrict__ colors,
                                               float* __restrict__ out) {
    __shared__ float2 colS[NCOL][12];
    __shared__ unsigned char tile[12][36];
    __shared__ float stage[NB * 8 * 96];   // 24 KB

    int tx = threadIdx.x, ty = threadIdx.y;
    int t = ty * 32 + tx;
    load_palette(colors, colS, t);

    int bi0 = blockIdx.y * 8, bj0 = blockIdx.x * 32;
    for (int q = t; q < 12 * 36; q += 256) {
        int r = q / 36, cc = q % 36;
        int gi = bi0 + r - 2, gj = bj0 + cc - 2;
        unsigned char v = 255;
        if ((unsigned)gi < (unsigned)NW && (unsigned)gj < (unsigned)NW)
            v = g_idx[gi * NW + gj];
        tile[r][cc] = v;
    }
    __syncthreads();

    unsigned long long acc[12];
    hist_dot(tile, colS, tx, ty, acc);

    float mn = __uint_as_float(g_omin);
    float mx = __uint_as_float(g_omax);
    float inv = 1.0f / (mx - mn);
    float kwi = 0.04f * inv;
    float off = -mn * inv;

    #pragma unroll
    for (int j = 0; j < 12; j++) {
        float a, b; unpack2(acc[j], a, b);
        int q0 = 2 * j, q1 = 2 * j + 1;
        stage[((q0 / 3) * 8 + ty) * 96 + tx * 3 + (q0 % 3)] = fmaf(a, kwi, off);
        stage[((q1 / 3) * 8 + ty) * 96 + tx * 3 + (q1 % 3)] = fmaf(b, kwi, off);
    }
    __syncthreads();

    // 1536 float4 chunks per block, 6 per thread, fully coalesced STG.128
    #pragma unroll
    for (int s = 0; s < 6; s++) {
        int m = t + 256 * s;          // 0..1535
        int b = m / 192;              // 8 rows * 24 chunks
        int rm = m % 192;
        int r = rm / 24, c4 = rm % 24;
        float4 v = *(const float4*)&stage[(b * 8 + r) * 96 + 4 * c4];
        long long base = (((long long)b * NW + (bi0 + r)) * NW + bj0) * 3 + 4 * c4;
        *(float4*)&out[base] = v;
    }
}

extern "C" void kernel_launch(void* const* d_in, const int* in_sizes, int n_in,
                              void* d_out, int out_size) {
    (void)in_sizes; (void)n_in; (void)out_size;
    const float* colors = (const float*)d_in[0];
    float* out = (float*)d_out;

    k_octaves<<<NOCT, NW>>>();
    k_nminmax<<<(NW * NW / 4) / 256, 256>>>();

    dim3 blk(32, 8);
    dim3 grd(NW / 32, NW / 8);
    k_blurA<<<grd, blk>>>(colors);
    k_blurB<<<grd, blk>>>(colors, out);
}